// round 2
// baseline (speedup 1.0000x reference)
#include <cuda_runtime.h>
#include <math.h>

// Cosine similarity per row: out[n] = dot(p[n], h[n]) / (max(||p||,eps) * max(||h||,eps))
// N = 65536 rows, D = 1024 floats.
// One CTA per row, 256 threads, each thread loads one float4 from each input.

#define D_DIM 1024
#define THREADS 256
#define EPS 1e-12f

__global__ __launch_bounds__(THREADS, 8)
void cosine_sim_kernel(const float4* __restrict__ p,
                       const float4* __restrict__ h,
                       float* __restrict__ out)
{
    const int row = blockIdx.x;
    const int t = threadIdx.x;
    // D/4 = 256 float4 per row == THREADS, so each thread loads exactly one.
    const long long idx = (long long)row * (D_DIM / 4) + t;

    float4 pv = p[idx];
    float4 hv = h[idx];

    float dot = pv.x * hv.x + pv.y * hv.y + pv.z * hv.z + pv.w * hv.w;
    float pp  = pv.x * pv.x + pv.y * pv.y + pv.z * pv.z + pv.w * pv.w;
    float hh  = hv.x * hv.x + hv.y * hv.y + hv.z * hv.z + hv.w * hv.w;

    // intra-warp reduce (3 values)
    #pragma unroll
    for (int offset = 16; offset > 0; offset >>= 1) {
        dot += __shfl_xor_sync(0xFFFFFFFFu, dot, offset);
        pp  += __shfl_xor_sync(0xFFFFFFFFu, pp,  offset);
        hh  += __shfl_xor_sync(0xFFFFFFFFu, hh,  offset);
    }

    // cross-warp reduce through shared memory: 8 warps
    __shared__ float s_dot[8], s_pp[8], s_hh[8];
    const int warp = t >> 5;
    const int lane = t & 31;
    if (lane == 0) {
        s_dot[warp] = dot;
        s_pp[warp]  = pp;
        s_hh[warp]  = hh;
    }
    __syncthreads();

    if (warp == 0) {
        float d2 = (lane < 8) ? s_dot[lane] : 0.0f;
        float p2 = (lane < 8) ? s_pp[lane]  : 0.0f;
        float h2 = (lane < 8) ? s_hh[lane]  : 0.0f;
        #pragma unroll
        for (int offset = 4; offset > 0; offset >>= 1) {
            d2 += __shfl_xor_sync(0xFFFFFFFFu, d2, offset);
            p2 += __shfl_xor_sync(0xFFFFFFFFu, p2, offset);
            h2 += __shfl_xor_sync(0xFFFFFFFFu, h2, offset);
        }
        if (lane == 0) {
            float pn = fmaxf(sqrtf(p2), EPS);
            float hn = fmaxf(sqrtf(h2), EPS);
            out[row] = d2 / (pn * hn);
        }
    }
}

extern "C" void kernel_launch(void* const* d_in, const int* in_sizes, int n_in,
                              void* d_out, int out_size) {
    const float4* p = (const float4*)d_in[0];
    const float4* h = (const float4*)d_in[1];
    float* out = (float*)d_out;

    const int n_rows = in_sizes[0] / D_DIM;  // 65536
    cosine_sim_kernel<<<n_rows, THREADS>>>(p, h, out);
}

// round 4
// speedup vs baseline: 1.0780x; 1.0780x over previous
#include <cuda_runtime.h>
#include <math.h>

// Cosine similarity per row: out[n] = dot(p[n],h[n]) / (max(||p||,eps)*max(||h||,eps))
// N = 65536 rows, D = 1024 floats (= 256 float4).
// One WARP per row: each lane loads 8 float4 from each input (front-batched,
// MLP=16), reduction is pure warp shuffles — no smem, no __syncthreads.

#define D_DIM 1024
#define F4_PER_ROW (D_DIM / 4)      // 256
#define THREADS 256                 // 8 warps -> 8 rows per CTA
#define ROWS_PER_CTA 8
#define F4_PER_LANE (F4_PER_ROW / 32)  // 8
#define EPS 1e-12f

__global__ __launch_bounds__(THREADS, 8)
void cosine_sim_warp_kernel(const float4* __restrict__ p,
                            const float4* __restrict__ h,
                            float* __restrict__ out)
{
    const int warp = threadIdx.x >> 5;
    const int lane = threadIdx.x & 31;
    const long long row = (long long)blockIdx.x * ROWS_PER_CTA + warp;

    const float4* __restrict__ prow = p + row * F4_PER_ROW;
    const float4* __restrict__ hrow = h + row * F4_PER_ROW;

    // Front-batch all 16 loads so the LSU queue sees max MLP before any
    // FMA dependency stalls the warp.
    float4 pv[F4_PER_LANE];
    float4 hv[F4_PER_LANE];
    #pragma unroll
    for (int i = 0; i < F4_PER_LANE; i++) {
        pv[i] = prow[lane + i * 32];
    }
    #pragma unroll
    for (int i = 0; i < F4_PER_LANE; i++) {
        hv[i] = hrow[lane + i * 32];
    }

    float dot = 0.0f, pp = 0.0f, hh = 0.0f;
    #pragma unroll
    for (int i = 0; i < F4_PER_LANE; i++) {
        dot = fmaf(pv[i].x, hv[i].x, dot);
        dot = fmaf(pv[i].y, hv[i].y, dot);
        dot = fmaf(pv[i].z, hv[i].z, dot);
        dot = fmaf(pv[i].w, hv[i].w, dot);
        pp  = fmaf(pv[i].x, pv[i].x, pp);
        pp  = fmaf(pv[i].y, pv[i].y, pp);
        pp  = fmaf(pv[i].z, pv[i].z, pp);
        pp  = fmaf(pv[i].w, pv[i].w, pp);
        hh  = fmaf(hv[i].x, hv[i].x, hh);
        hh  = fmaf(hv[i].y, hv[i].y, hh);
        hh  = fmaf(hv[i].z, hv[i].z, hh);
        hh  = fmaf(hv[i].w, hv[i].w, hh);
    }

    // Warp-level tree reduction of the three partials.
    #pragma unroll
    for (int offset = 16; offset > 0; offset >>= 1) {
        dot += __shfl_xor_sync(0xFFFFFFFFu, dot, offset);
        pp  += __shfl_xor_sync(0xFFFFFFFFu, pp,  offset);
        hh  += __shfl_xor_sync(0xFFFFFFFFu, hh,  offset);
    }

    if (lane == 0) {
        float pn = fmaxf(sqrtf(pp), EPS);
        float hn = fmaxf(sqrtf(hh), EPS);
        out[row] = dot / (pn * hn);
    }
}

extern "C" void kernel_launch(void* const* d_in, const int* in_sizes, int n_in,
                              void* d_out, int out_size) {
    const float4* p = (const float4*)d_in[0];
    const float4* h = (const float4*)d_in[1];
    float* out = (float*)d_out;

    const int n_rows = in_sizes[0] / D_DIM;          // 65536
    const int n_blocks = n_rows / ROWS_PER_CTA;      // 8192
    cosine_sim_warp_kernel<<<n_blocks, THREADS>>>(p, h, out);
}

// round 5
// speedup vs baseline: 1.1070x; 1.0268x over previous
#include <cuda_runtime.h>
#include <math.h>

// Cosine similarity per row: out[n] = dot(p[n],h[n]) / (max(||p||,eps)*max(||h||,eps))
// N = 65536 rows, D = 1024 floats (= 256 float4).
// One WARP per row: each lane loads 8 float4 from each input, front-batched
// (16 independent LDG.128 in flight). launch_bounds occupancy relaxed to 4
// CTAs/SM so ptxas has a 64-register budget and does NOT interleave/spill the
// load batch (the R2 kernel was silently capped at 32 regs -> MLP ~4).
// __ldcs: streaming loads, no reuse -> evict-first.

#define D_DIM 1024
#define F4_PER_ROW (D_DIM / 4)      // 256
#define THREADS 256                 // 8 warps -> 8 rows per CTA
#define ROWS_PER_CTA 8
#define F4_PER_LANE (F4_PER_ROW / 32)  // 8
#define EPS 1e-12f

__global__ __launch_bounds__(THREADS, 4)
void cosine_sim_warp_kernel(const float4* __restrict__ p,
                            const float4* __restrict__ h,
                            float* __restrict__ out)
{
    const int warp = threadIdx.x >> 5;
    const int lane = threadIdx.x & 31;
    const long long row = (long long)blockIdx.x * ROWS_PER_CTA + warp;

    const float4* __restrict__ prow = p + row * F4_PER_ROW;
    const float4* __restrict__ hrow = h + row * F4_PER_ROW;

    // Front-batch all 16 loads (independent, streaming).
    float4 pv[F4_PER_LANE];
    float4 hv[F4_PER_LANE];
    #pragma unroll
    for (int i = 0; i < F4_PER_LANE; i++) {
        pv[i] = __ldcs(&prow[lane + i * 32]);
    }
    #pragma unroll
    for (int i = 0; i < F4_PER_LANE; i++) {
        hv[i] = __ldcs(&hrow[lane + i * 32]);
    }

    float dot = 0.0f, pp = 0.0f, hh = 0.0f;
    #pragma unroll
    for (int i = 0; i < F4_PER_LANE; i++) {
        dot = fmaf(pv[i].x, hv[i].x, dot);
        dot = fmaf(pv[i].y, hv[i].y, dot);
        dot = fmaf(pv[i].z, hv[i].z, dot);
        dot = fmaf(pv[i].w, hv[i].w, dot);
        pp  = fmaf(pv[i].x, pv[i].x, pp);
        pp  = fmaf(pv[i].y, pv[i].y, pp);
        pp  = fmaf(pv[i].z, pv[i].z, pp);
        pp  = fmaf(pv[i].w, pv[i].w, pp);
        hh  = fmaf(hv[i].x, hv[i].x, hh);
        hh  = fmaf(hv[i].y, hv[i].y, hh);
        hh  = fmaf(hv[i].z, hv[i].z, hh);
        hh  = fmaf(hv[i].w, hv[i].w, hh);
    }

    // Warp-level tree reduction of the three partials.
    #pragma unroll
    for (int offset = 16; offset > 0; offset >>= 1) {
        dot += __shfl_xor_sync(0xFFFFFFFFu, dot, offset);
        pp  += __shfl_xor_sync(0xFFFFFFFFu, pp,  offset);
        hh  += __shfl_xor_sync(0xFFFFFFFFu, hh,  offset);
    }

    if (lane == 0) {
        float pn = fmaxf(sqrtf(pp), EPS);
        float hn = fmaxf(sqrtf(hh), EPS);
        out[row] = dot / (pn * hn);
    }
}

extern "C" void kernel_launch(void* const* d_in, const int* in_sizes, int n_in,
                              void* d_out, int out_size) {
    const float4* p = (const float4*)d_in[0];
    const float4* h = (const float4*)d_in[1];
    float* out = (float*)d_out;

    const int n_rows = in_sizes[0] / D_DIM;          // 65536
    const int n_blocks = n_rows / ROWS_PER_CTA;      // 8192
    cosine_sim_warp_kernel<<<n_blocks, THREADS>>>(p, h, out);
}